// round 11
// baseline (speedup 1.0000x reference)
#include <cuda_runtime.h>

// ResidualEmbedding: per-frame Burg LPC (order 12) residual, sign-modulated embed.
// R11: R10 core (4 frames/warp, 8 lanes/frame, 20 samples/lane) with:
//  - a[] coefficients in per-frame SHARED memory, cooperatively updated
//    (frees 13 registers; moves the replicated a-update FMAs off the fma pipe)
//  - per-block Hann window table (no per-lane __cosf)
//  - sliding-window FIR (16-float window, 4 outputs/step, direct STG.128)
//  - launch_bounds(256,5): 51-reg target -> 5 blocks/SM (40 warps)

namespace {

constexpr int FRAME   = 160;
constexpr int ORDER   = 12;
constexpr int NFRAMES = 4096 * 15;       // 61440
constexpr int WPB     = 8;               // warps per block (32 frames/block)
constexpr int THREADS = WPB * 32;
constexpr int ROW     = 176;             // 12 halo + 160 + 4 pad (floats)
constexpr unsigned FULL = 0xffffffffu;

__device__ __forceinline__ float grp_sum(float v) {
#pragma unroll
    for (int o = 4; o > 0; o >>= 1) v += __shfl_xor_sync(FULL, v, o);
    return v;
}

__device__ __forceinline__ float fast_rcp(float x) {
    float r; asm("rcp.approx.f32 %0, %1;" : "=f"(r) : "f"(x)); return r;
}

__global__ __launch_bounds__(THREADS, 5) void burg_residual_kernel(
    const int*   __restrict__ bits,
    const float* __restrict__ pcm,
    const float* __restrict__ alpha_p,
    float*       __restrict__ out)
{
    const int warp   = threadIdx.x >> 5;
    const int lane   = threadIdx.x & 31;
    const int frame0 = (blockIdx.x * WPB + warp) * 4;   // exact grid
    const int sub    = lane >> 3;        // frame within warp
    const int lh     = lane & 7;         // lane within frame
    const int jb     = 20 * lh;          // my contiguous j-range start

    __shared__ float win[FRAME];
    __shared__ float Xs[WPB][4][ROW];
    __shared__ float Ac[WPB][4][16];     // a[0..12] (+3 zero pad) per frame
    float* __restrict__ P = &Xs[warp][sub][0];   // sample j at P[12+j]
    float* __restrict__ A = &Ac[warp][sub][0];

    // ---- Hann window once per block: w[j] = 0.5 - 0.5*cos(2*pi*j/159) ----
    if (threadIdx.x < FRAME)
        win[threadIdx.x] =
            0.5f - 0.5f * __cosf((6.283185307179586f / 159.0f) * (float)threadIdx.x);
    __syncthreads();

    // ---- Load 20 contiguous samples (5 x LDG.128), stash + zero halo ----
    const float* __restrict__ src = pcm + (long long)(frame0 + sub) * FRAME + jb;
    float b[20];     // will become windowed xw, then Burg b
    {
        const float4* s4 = (const float4*)src;
        float4*       Pd = (float4*)(P + 12 + jb);
        const float4* W4 = (const float4*)(win + jb);
#pragma unroll
        for (int k = 0; k < 5; ++k) {
            const float4 v = s4[k];
            Pd[k] = v;                                  // raw samples for FIR
            const float4 w = W4[k];
            b[4*k]   = v.x * w.x;
            b[4*k+1] = v.y * w.y;
            b[4*k+2] = v.z * w.z;
            b[4*k+3] = v.w * w.w;
        }
        if (lh < 3) ((float4*)P)[lh] = make_float4(0.f, 0.f, 0.f, 0.f);
    }

    // ---- a in shared: a[0]=1, rest 0 (16 entries incl. pad) ----
    A[lh]     = (lh == 0) ? 1.f : 0.f;
    A[lh + 8] = 0.f;

    // ---- Init: f[j]=xw[j+1] (valid j<=158); j=159 entries = 0 ----
    float f[20];
#pragma unroll
    for (int c = 0; c < 19; ++c) f[c] = b[c + 1];
    {
        const float nxt = __shfl_sync(FULL, b[0], lane + 1);
        f[19] = (lh == 7) ? 0.f : nxt;
    }
    if (lh == 7) b[19] = 0.f;

    float den;
    {
        float p0 = 0.f, p1 = 0.f;
#pragma unroll
        for (int c = 0; c < 20; c += 2) {
            p0 = fmaf(f[c],   f[c],   fmaf(b[c],   b[c],   p0));
            p1 = fmaf(f[c+1], f[c+1], fmaf(b[c+1], b[c+1], p1));
        }
        den = grp_sum(p0 + p1);
    }
    float inv_den = fast_rcp(den);
    __syncwarp();    // A init visible

    // ---- Burg recursion. Invariant at iter i entry: f[j]=b[j]=0 for j>=159-i ----
#pragma unroll
    for (int i = 0; i < ORDER; ++i) {
        float p0 = 0.f, p1 = 0.f;
#pragma unroll
        for (int c = 0; c < 20; c += 2) {
            p0 = fmaf(f[c],   b[c],   p0);
            p1 = fmaf(f[c+1], b[c+1], p1);
        }
        const float s = grp_sum(p0 + p1);
        const float r = -2.f * s * inv_den;      // inv_den ready since last iter

        // in-place: f <- f + r*b ; b <- b + r*f_old
#pragma unroll
        for (int c = 0; c < 20; ++c) {
            const float fo = f[c];
            f[c] = fmaf(r, b[c], f[c]);
            b[c] = fmaf(r, fo,   b[c]);
        }

        // den_{i+1} = (1-r^2)*den - b_new[158-i]^2 - f_new[0]^2
        const int jl = 158 - i, Ll = jl / 20, cl = jl % 20;   // compile-time
        const float nf19 = __shfl_sync(FULL, f[0], lane + 1); // for the shift
        const float t0   = __shfl_sync(FULL, f[0], lane & ~7);
        const float ub   = __shfl_sync(FULL, b[cl], (lane & ~7) | Ll);
        den = (1.f - r * r) * den - ub * ub - t0 * t0;
        inv_den = fast_rcp(den);                 // off-chain: overlaps next dot

        // f' = shift-by-1(f); b': zero newly-invalid element
#pragma unroll
        for (int c = 0; c < 19; ++c) f[c] = f[c + 1];
        f[19] = (lh == 7) ? 0.f : nf19;
        if (lh == Ll) b[cl] = 0.f;

        // a[:i+2] += r * reverse(a[:i+2]) -- cooperative in shared
        // lane lh owns k0=lh, k8=lh+8. Read old values, syncwarp, write.
        {
            const int k0 = lh, k8 = lh + 8;
            const int r0i = i + 1 - k0;          // valid iff >= 0
            const int r8i = i + 1 - k8;
            const float a0 = A[k0];
            const float a8 = A[k8];
            const float v0 = (r0i >= 0) ? A[r0i] : 0.f;
            const float v8 = (r8i >= 0) ? A[r8i] : 0.f;
            __syncwarp();
            if (r0i >= 0) A[k0] = fmaf(r, v0, a0);
            if (r8i >= 0) A[k8] = fmaf(r, v8, a8);
            __syncwarp();
        }
    }

    // ---- FIR on raw samples: sliding 16-float window, 4 outputs per step ----
    float ar[ORDER + 1];
    {
        const float4* Af = (const float4*)A;
        const float4 a0 = Af[0], a1 = Af[1], a2 = Af[2];
        ar[0]=a0.x; ar[1]=a0.y; ar[2]=a0.z; ar[3]=a0.w;
        ar[4]=a1.x; ar[5]=a1.y; ar[6]=a1.z; ar[7]=a1.w;
        ar[8]=a2.x; ar[9]=a2.y; ar[10]=a2.z; ar[11]=a2.w;
        ar[12] = A[12];
    }

    const float sgn  = 2.f * (float)__ldg(&bits[frame0 + sub]) - 1.f;
    const float coef = __ldg(alpha_p) * sgn;
    float* __restrict__ dst = out + (long long)(frame0 + sub) * FRAME + jb;

    float w[16];     // P[jb + 4g .. jb + 4g + 15] = X[jb-12+4g .. jb+3+4g]
    {
        const float4* W = (const float4*)(P + jb);
#pragma unroll
        for (int k = 0; k < 4; ++k) {
            const float4 v = W[k];
            w[4*k]=v.x; w[4*k+1]=v.y; w[4*k+2]=v.z; w[4*k+3]=v.w;
        }
    }

#pragma unroll
    for (int g = 0; g < 5; ++g) {
        float4 o;
        float* op = &o.x;
#pragma unroll
        for (int t = 0; t < 4; ++t) {
            const float xc = w[12 + t];          // X[jb + 4g + t]
            float acc = ar[0] * xc;
#pragma unroll
            for (int k = 1; k <= ORDER; ++k)
                acc = fmaf(ar[k], w[12 + t - k], acc);
            op[t] = fmaf(coef, acc, xc);
        }
        ((float4*)dst)[g] = o;
        if (g < 4) {   // slide window by 4
            const float4 v = ((const float4*)(P + jb))[4 + g];
#pragma unroll
            for (int k = 0; k < 12; ++k) w[k] = w[k + 4];
            w[12]=v.x; w[13]=v.y; w[14]=v.z; w[15]=v.w;
        }
    }
}

} // namespace

extern "C" void kernel_launch(void* const* d_in, const int* in_sizes, int n_in,
                              void* d_out, int out_size)
{
    const int*   bits  = (const int*)  d_in[0];
    const float* pcm   = (const float*)d_in[1];
    const float* alpha = (const float*)d_in[2];
    float*       out   = (float*)d_out;

    const int grid = NFRAMES / (WPB * 4);   // 1920 blocks
    burg_residual_kernel<<<grid, THREADS>>>(bits, pcm, alpha, out);
}

// round 12
// speedup vs baseline: 1.2447x; 1.2447x over previous
#include <cuda_runtime.h>

// ResidualEmbedding: per-frame Burg LPC (order 12) residual, sign-modulated embed.
// R12: exact R10 core (4 frames/warp, 8 lanes/frame, 20 samples/lane, a[] in regs,
// hoisted rcp) + two register-neutral cuts:
//  - per-block Hann window table in shared (kills 20 MUFU __cosf/lane)
//  - bits/alpha prefetched before the Burg loop (hides LDG latency)
// R11 lesson: a[] stays in registers; nothing enters the serial chain.

namespace {

constexpr int FRAME   = 160;
constexpr int ORDER   = 12;
constexpr int NFRAMES = 4096 * 15;       // 61440
constexpr int WPB     = 8;               // warps per block (32 frames/block)
constexpr int THREADS = WPB * 32;
constexpr int ROW     = 176;             // 12 halo + 160 + 4 pad (floats, 16B-aligned)
constexpr unsigned FULL = 0xffffffffu;

// reduce over each 8-lane group independently (4 frames at once)
__device__ __forceinline__ float grp_sum(float v) {
#pragma unroll
    for (int o = 4; o > 0; o >>= 1) v += __shfl_xor_sync(FULL, v, o);
    return v;
}

__device__ __forceinline__ float fast_rcp(float x) {
    float r; asm("rcp.approx.f32 %0, %1;" : "=f"(r) : "f"(x)); return r;
}

__global__ __launch_bounds__(THREADS) void burg_residual_kernel(
    const int*   __restrict__ bits,
    const float* __restrict__ pcm,
    const float* __restrict__ alpha_p,
    float*       __restrict__ out)
{
    const int warp   = threadIdx.x >> 5;
    const int lane   = threadIdx.x & 31;
    const int frame0 = (blockIdx.x * WPB + warp) * 4;   // exact grid
    const int sub    = lane >> 3;        // frame within warp
    const int lh     = lane & 7;         // lane within frame
    const int jb     = 20 * lh;          // my contiguous j-range start

    __shared__ float win[FRAME];
    __shared__ float Xs[WPB][4][ROW];
    float* __restrict__ P = &Xs[warp][sub][0];          // sample j at P[12+j]

    // ---- Hann window once per block: w[j] = 0.5 - 0.5*cos(2*pi*j/159) ----
    if (threadIdx.x < FRAME)
        win[threadIdx.x] =
            0.5f - 0.5f * __cosf((6.283185307179586f / 159.0f) * (float)threadIdx.x);
    __syncthreads();

    // ---- Prefetch the scalars needed after the Burg loop ----
    const float sgn   = 2.f * (float)__ldg(&bits[frame0 + sub]) - 1.f;
    const float alpha = __ldg(alpha_p);

    // ---- Vectorized load + window from table; stash raw + zero halo ----
    const float* __restrict__ src = pcm + (long long)(frame0 + sub) * FRAME + jb;
    float b[20];                          // windowed samples -> Burg b
    {
        const float4* s4 = (const float4*)src;
        float4*       Pd = (float4*)(P + 12 + jb);
        const float4* W4 = (const float4*)(win + jb);
#pragma unroll
        for (int k = 0; k < 5; ++k) {
            const float4 v = s4[k];
            Pd[k] = v;                                   // raw samples for FIR
            const float4 w = W4[k];
            b[4*k]   = v.x * w.x;
            b[4*k+1] = v.y * w.y;
            b[4*k+2] = v.z * w.z;
            b[4*k+3] = v.w * w.w;
        }
        if (lh < 3) ((float4*)P)[lh] = make_float4(0.f, 0.f, 0.f, 0.f);
    }

    // ---- Init: f[j]=xw[j+1] (valid j<=158); j=159 entries = 0 ----
    float f[20];
#pragma unroll
    for (int c = 0; c < 19; ++c) f[c] = b[c + 1];
    {
        const float nxt = __shfl_sync(FULL, b[0], lane + 1);
        f[19] = (lh == 7) ? 0.f : nxt;
    }
    if (lh == 7) b[19] = 0.f;

    float den;
    {
        float p0 = 0.f, p1 = 0.f;
#pragma unroll
        for (int c = 0; c < 20; c += 2) {
            p0 = fmaf(f[c],   f[c],   fmaf(b[c],   b[c],   p0));
            p1 = fmaf(f[c+1], f[c+1], fmaf(b[c+1], b[c+1], p1));
        }
        den = grp_sum(p0 + p1);
    }
    float inv_den = fast_rcp(den);

    float a[ORDER + 1];
    a[0] = 1.f;
#pragma unroll
    for (int k = 1; k <= ORDER; ++k) a[k] = 0.f;

    // ---- Burg recursion. Invariant at iter i entry: f[j]=b[j]=0 for j>=159-i ----
#pragma unroll
    for (int i = 0; i < ORDER; ++i) {
        float p0 = 0.f, p1 = 0.f;
#pragma unroll
        for (int c = 0; c < 20; c += 2) {
            p0 = fmaf(f[c],   b[c],   p0);
            p1 = fmaf(f[c+1], b[c+1], p1);
        }
        const float s = grp_sum(p0 + p1);
        const float r = -2.f * s * inv_den;      // inv_den ready since last iter

        // in-place: f <- f + r*b ; b <- b + r*f_old
#pragma unroll
        for (int c = 0; c < 20; ++c) {
            const float fo = f[c];
            f[c] = fmaf(r, b[c], f[c]);
            b[c] = fmaf(r, fo,   b[c]);
        }

        // den_{i+1} = (1-r^2)*den - b_new[158-i]^2 - f_new[0]^2
        const int jl = 158 - i, Ll = jl / 20, cl = jl % 20;   // compile-time
        const float nf19 = __shfl_sync(FULL, f[0], lane + 1); // for the shift
        const float t0   = __shfl_sync(FULL, f[0], lane & ~7);
        const float ub   = __shfl_sync(FULL, b[cl], (lane & ~7) | Ll);
        den = (1.f - r * r) * den - ub * ub - t0 * t0;
        inv_den = fast_rcp(den);                 // off-chain: overlaps next dot

        // f' = shift-by-1(f); b': zero newly-invalid element
#pragma unroll
        for (int c = 0; c < 19; ++c) f[c] = f[c + 1];
        f[19] = (lh == 7) ? 0.f : nf19;
        if (lh == Ll) b[cl] = 0.f;

        // a[:i+2] += r * reverse(a[:i+2])  -- pairwise in place
#pragma unroll
        for (int k = 0; 2 * k <= i + 1; ++k) {
            const int k2 = i + 1 - k;
            if (k2 == k) {
                a[k] = a[k] + r * a[k];
            } else {
                const float tmp = a[k];
                a[k]  = fmaf(r, a[k2], a[k]);
                a[k2] = fmaf(r, tmp,  a[k2]);
            }
        }
    }

    // ---- FIR on raw samples: 32-float register window (8 x LDS.128) ----
    __syncwarp();   // halo/sample STS visible across the group
    float xf[32];   // X[jb-12 .. jb+19]
    {
        const float4* W = (const float4*)(P + jb);   // = &P[12 + jb - 12]
#pragma unroll
        for (int k = 0; k < 8; ++k) {
            const float4 v = W[k];
            xf[4*k] = v.x; xf[4*k+1] = v.y; xf[4*k+2] = v.z; xf[4*k+3] = v.w;
        }
    }

    const float coef = alpha * sgn;

    float o[20];
#pragma unroll
    for (int c = 0; c < 20; ++c) {
        float acc = a[0] * xf[12 + c];
#pragma unroll
        for (int k = 1; k <= ORDER; ++k)
            acc = fmaf(a[k], xf[12 + c - k], acc);
        o[c] = fmaf(coef, acc, xf[12 + c]);
    }

    // ---- Vectorized store (5 x STG.128) ----
    float* __restrict__ dst = out + (long long)(frame0 + sub) * FRAME + jb;
    float4* d4 = (float4*)dst;
#pragma unroll
    for (int k = 0; k < 5; ++k)
        d4[k] = make_float4(o[4*k], o[4*k+1], o[4*k+2], o[4*k+3]);
}

} // namespace

extern "C" void kernel_launch(void* const* d_in, const int* in_sizes, int n_in,
                              void* d_out, int out_size)
{
    const int*   bits  = (const int*)  d_in[0];
    const float* pcm   = (const float*)d_in[1];
    const float* alpha = (const float*)d_in[2];
    float*       out   = (float*)d_out;

    const int grid = NFRAMES / (WPB * 4);   // 1920 blocks
    burg_residual_kernel<<<grid, THREADS>>>(bits, pcm, alpha, out);
}